// round 4
// baseline (speedup 1.0000x reference)
#include <cuda_runtime.h>

#define B_    4
#define S_    2048
#define D_    1024
#define H_    16
#define HD_   64
#define MLP_  4096
#define MROWS (B_*S_)   // 8192

// Scratch (device globals — no runtime allocation allowed)
__device__ float g_xn[(size_t)MROWS * D_];
__device__ float g_h [(size_t)MROWS * MLP_];
__device__ float g_q [(size_t)MROWS * D_];
__device__ float g_k [(size_t)MROWS * D_];
__device__ float g_v [(size_t)MROWS * D_];
__device__ float g_av[(size_t)MROWS * D_];

// ---------------------------------------------------------------------------
// RMSNorm: one block per row (1024 elems), 256 threads, float4 per thread
// ---------------------------------------------------------------------------
__global__ __launch_bounds__(256) void rmsnorm_kernel(
    const float* __restrict__ x, const float* __restrict__ scale,
    float* __restrict__ out)
{
    int row = blockIdx.x;
    const float4* xr = (const float4*)(x + (size_t)row * D_);
    float4 v = xr[threadIdx.x];
    float s = v.x*v.x + v.y*v.y + v.z*v.z + v.w*v.w;

    __shared__ float red[256];
    red[threadIdx.x] = s;
    __syncthreads();
    #pragma unroll
    for (int off = 128; off > 0; off >>= 1) {
        if (threadIdx.x < off) red[threadIdx.x] += red[threadIdx.x + off];
        __syncthreads();
    }
    float inv = rsqrtf(red[0] * (1.0f / D_) + 1e-6f);

    float4 sc = ((const float4*)scale)[threadIdx.x];
    float4 o;
    o.x = v.x * inv * sc.x;
    o.y = v.y * inv * sc.y;
    o.z = v.z * inv * sc.z;
    o.w = v.w * inv * sc.w;
    ((float4*)(out + (size_t)row * D_))[threadIdx.x] = o;
}

// ---------------------------------------------------------------------------
// SGEMM 128x128x8, 256 threads, 8x8 microtile per thread.
// EPI: 0 = plain store, 1 = gelu(tanh approx), 2 = +bias1+bias2+residual,
//      3 = accumulate into C
// ---------------------------------------------------------------------------
template<int EPI>
__global__ __launch_bounds__(256) void sgemm_kernel(
    const float* __restrict__ A, const float* __restrict__ Bm,
    float* __restrict__ C,
    const float* __restrict__ bias1, const float* __restrict__ bias2,
    const float* __restrict__ resid,
    int M, int N, int K)
{
    __shared__ float As[8][128];
    __shared__ float Bs[8][128];

    int tid = threadIdx.x;
    int bm = blockIdx.y, bn = blockIdx.x;

    int arow = tid >> 1;          // 0..127
    int acol = (tid & 1) * 4;     // 0 or 4
    int brow = tid >> 5;          // 0..7
    int bcol = (tid & 31) * 4;    // 0..124

    const float* Aptr = A + (size_t)(bm * 128 + arow) * K + acol;
    const float* Bptr = Bm + (size_t)brow * N + bn * 128 + bcol;

    int tx = tid & 15, ty = tid >> 4;

    float acc[8][8];
    #pragma unroll
    for (int i = 0; i < 8; i++)
        #pragma unroll
        for (int j = 0; j < 8; j++) acc[i][j] = 0.0f;

    for (int k0 = 0; k0 < K; k0 += 8) {
        float4 a = *(const float4*)(Aptr + k0);
        float4 b = *(const float4*)(Bptr + (size_t)k0 * N);
        As[acol + 0][arow] = a.x;
        As[acol + 1][arow] = a.y;
        As[acol + 2][arow] = a.z;
        As[acol + 3][arow] = a.w;
        *(float4*)&Bs[brow][bcol] = b;
        __syncthreads();

        #pragma unroll
        for (int k = 0; k < 8; k++) {
            float ar[8], br[8];
            #pragma unroll
            for (int i = 0; i < 8; i++) ar[i] = As[k][ty * 8 + i];
            #pragma unroll
            for (int j = 0; j < 8; j++) br[j] = Bs[k][tx * 8 + j];
            #pragma unroll
            for (int i = 0; i < 8; i++)
                #pragma unroll
                for (int j = 0; j < 8; j++)
                    acc[i][j] = fmaf(ar[i], br[j], acc[i][j]);
        }
        __syncthreads();
    }

    #pragma unroll
    for (int i = 0; i < 8; i++) {
        int row = bm * 128 + ty * 8 + i;
        #pragma unroll
        for (int j = 0; j < 8; j++) {
            int col = bn * 128 + tx * 8 + j;
            size_t idx = (size_t)row * N + col;
            float val = acc[i][j];
            if (EPI == 1) {
                float t = 0.7978845608028654f * (val + 0.044715f * val * val * val);
                val = 0.5f * val * (1.0f + tanhf(t));
            } else if (EPI == 2) {
                val += bias1[col] + bias2[col] + resid[idx];
            } else if (EPI == 3) {
                val += C[idx];
            }
            C[idx] = val;
        }
    }
}

// ---------------------------------------------------------------------------
// Flash attention (fp32). Grid: (S/128, H, B). 128 threads, one query row per
// thread. K/V staged in SMEM in BK=32 tiles; all compute reads are broadcasts.
// ---------------------------------------------------------------------------
__global__ __launch_bounds__(128) void attn_kernel(
    const float* __restrict__ q, const float* __restrict__ k,
    const float* __restrict__ v, float* __restrict__ av)
{
    int h = blockIdx.y, b = blockIdx.z;
    int tid = threadIdx.x;
    int qi = blockIdx.x * 128 + tid;

    __shared__ float Ks[32][64];
    __shared__ float Vs[32][64];

    const float* qptr = q + ((size_t)(b * S_ + qi)) * D_ + h * HD_;
    float4 qr[16];
    #pragma unroll
    for (int i = 0; i < 16; i++) qr[i] = ((const float4*)qptr)[i];

    float4 acc[16];
    #pragma unroll
    for (int i = 0; i < 16; i++) acc[i] = make_float4(0.f, 0.f, 0.f, 0.f);

    float m = -1e30f, l = 0.0f;
    const float scale = 0.125f;  // 1/sqrt(64)

    int r = tid >> 2;            // 0..31  (4 threads per K/V row)
    int c = (tid & 3) * 16;      // 0,16,32,48

    for (int kt = 0; kt < S_; kt += 32) {
        __syncthreads();
        {
            const float* kp = k + ((size_t)(b * S_ + kt + r)) * D_ + h * HD_ + c;
            const float* vp = v + ((size_t)(b * S_ + kt + r)) * D_ + h * HD_ + c;
            #pragma unroll
            for (int i = 0; i < 4; i++) {
                *(float4*)&Ks[r][c + 4 * i] = ((const float4*)kp)[i];
                *(float4*)&Vs[r][c + 4 * i] = ((const float4*)vp)[i];
            }
        }
        __syncthreads();

        float s[32];
        float tmax = -1e30f;
        #pragma unroll
        for (int j = 0; j < 32; j++) {
            const float4* kr = (const float4*)Ks[j];
            float d0 = 0.f;
            #pragma unroll
            for (int i = 0; i < 16; i++) {
                float4 kk = kr[i];
                d0 = fmaf(qr[i].x, kk.x, d0);
                d0 = fmaf(qr[i].y, kk.y, d0);
                d0 = fmaf(qr[i].z, kk.z, d0);
                d0 = fmaf(qr[i].w, kk.w, d0);
            }
            s[j] = d0 * scale;
            tmax = fmaxf(tmax, s[j]);
        }

        float mnew = fmaxf(m, tmax);
        float corr = __expf(m - mnew);
        l *= corr;
        #pragma unroll
        for (int i = 0; i < 16; i++) {
            acc[i].x *= corr; acc[i].y *= corr;
            acc[i].z *= corr; acc[i].w *= corr;
        }
        m = mnew;

        #pragma unroll
        for (int j = 0; j < 32; j++) {
            float p = __expf(s[j] - m);
            l += p;
            const float4* vr = (const float4*)Vs[j];
            #pragma unroll
            for (int i = 0; i < 16; i++) {
                float4 vv = vr[i];
                acc[i].x = fmaf(p, vv.x, acc[i].x);
                acc[i].y = fmaf(p, vv.y, acc[i].y);
                acc[i].z = fmaf(p, vv.z, acc[i].z);
                acc[i].w = fmaf(p, vv.w, acc[i].w);
            }
        }
    }

    float invl = 1.0f / l;
    float* op = av + ((size_t)(b * S_ + qi)) * D_ + h * HD_;
    #pragma unroll
    for (int i = 0; i < 16; i++) {
        float4 o;
        o.x = acc[i].x * invl; o.y = acc[i].y * invl;
        o.z = acc[i].z * invl; o.w = acc[i].w * invl;
        ((float4*)op)[i] = o;
    }
}

// ---------------------------------------------------------------------------
// Launch
// ---------------------------------------------------------------------------
extern "C" void kernel_launch(void* const* d_in, const int* in_sizes, int n_in,
                              void* d_out, int out_size)
{
    const float* x          = (const float*)d_in[0];
    const float* pns        = (const float*)d_in[1];
    const float* w_mlp_in   = (const float*)d_in[2];
    const float* wq         = (const float*)d_in[3];
    const float* wk         = (const float*)d_in[4];
    const float* wv         = (const float*)d_in[5];
    const float* w_mlp_out  = (const float*)d_in[6];
    const float* b_mlp_out  = (const float*)d_in[7];
    const float* w_attn_out = (const float*)d_in[8];
    const float* b_attn_out = (const float*)d_in[9];
    float* out = (float*)d_out;

    float *xn, *hbuf, *q, *k, *v, *av;
    cudaGetSymbolAddress((void**)&xn,   g_xn);
    cudaGetSymbolAddress((void**)&hbuf, g_h);
    cudaGetSymbolAddress((void**)&q,    g_q);
    cudaGetSymbolAddress((void**)&k,    g_k);
    cudaGetSymbolAddress((void**)&v,    g_v);
    cudaGetSymbolAddress((void**)&av,   g_av);

    // 1. RMSNorm
    rmsnorm_kernel<<<MROWS, 256>>>(x, pns, xn);

    // 2. h = gelu(xn @ w_mlp_in)   [8192, 4096]
    dim3 g_mlp(MLP_ / 128, MROWS / 128);
    sgemm_kernel<1><<<g_mlp, 256>>>(xn, w_mlp_in, hbuf,
                                    nullptr, nullptr, nullptr,
                                    MROWS, MLP_, D_);

    // 3. q/k/v = xn @ w{q,k,v}    [8192, 1024] each
    dim3 g_d(D_ / 128, MROWS / 128);
    sgemm_kernel<0><<<g_d, 256>>>(xn, wq, q, nullptr, nullptr, nullptr,
                                  MROWS, D_, D_);
    sgemm_kernel<0><<<g_d, 256>>>(xn, wk, k, nullptr, nullptr, nullptr,
                                  MROWS, D_, D_);
    sgemm_kernel<0><<<g_d, 256>>>(xn, wv, v, nullptr, nullptr, nullptr,
                                  MROWS, D_, D_);

    // 4. attention -> av  [8192, 1024] (cols = h*64+hd)
    dim3 g_attn(S_ / 128, H_, B_);
    attn_kernel<<<g_attn, 128>>>(q, k, v, av);

    // 5. out = residual + h @ w_mlp_out + b_mlp_out + b_attn_out
    sgemm_kernel<2><<<g_d, 256>>>(hbuf, w_mlp_out, out,
                                  b_mlp_out, b_attn_out, x,
                                  MROWS, D_, MLP_);

    // 6. out += av @ w_attn_out
    sgemm_kernel<3><<<g_d, 256>>>(av, w_attn_out, out,
                                  nullptr, nullptr, nullptr,
                                  MROWS, D_, D_);
}

// round 5
// speedup vs baseline: 1.1721x; 1.1721x over previous
#include <cuda_runtime.h>
#include <cstdint>

#define B_    4
#define S_    2048
#define D_    1024
#define H_    16
#define HD_   64
#define MLP_  4096
#define MROWS (B_*S_)   // 8192

// Scratch (device globals — no runtime allocation allowed)
__device__ float g_xn[(size_t)MROWS * D_];
__device__ float g_h [(size_t)MROWS * MLP_];
__device__ float g_q [(size_t)MROWS * D_];
__device__ float g_k [(size_t)MROWS * D_];
__device__ float g_v [(size_t)MROWS * D_];
__device__ float g_av[(size_t)MROWS * D_];

// ---------------------------------------------------------------------------
// RMSNorm: one block per row (1024 elems), 256 threads, float4 per thread
// ---------------------------------------------------------------------------
__global__ __launch_bounds__(256) void rmsnorm_kernel(
    const float* __restrict__ x, const float* __restrict__ scale,
    float* __restrict__ out)
{
    int row = blockIdx.x;
    const float4* xr = (const float4*)(x + (size_t)row * D_);
    float4 v = xr[threadIdx.x];
    float s = v.x*v.x + v.y*v.y + v.z*v.z + v.w*v.w;

    __shared__ float red[256];
    red[threadIdx.x] = s;
    __syncthreads();
    #pragma unroll
    for (int off = 128; off > 0; off >>= 1) {
        if (threadIdx.x < off) red[threadIdx.x] += red[threadIdx.x + off];
        __syncthreads();
    }
    float inv = rsqrtf(red[0] * (1.0f / D_) + 1e-6f);

    float4 sc = ((const float4*)scale)[threadIdx.x];
    float4 o;
    o.x = v.x * inv * sc.x;
    o.y = v.y * inv * sc.y;
    o.z = v.z * inv * sc.z;
    o.w = v.w * inv * sc.w;
    ((float4*)(out + (size_t)row * D_))[threadIdx.x] = o;
}

// ---------------------------------------------------------------------------
// TF32 helpers (3xTF32 split: hi = tf32(v), lo = tf32(v - hi))
// ---------------------------------------------------------------------------
__device__ __forceinline__ uint32_t f2tf(float x) {
    uint32_t r;
    asm("cvt.rna.tf32.f32 %0, %1;" : "=r"(r) : "f"(x));
    return r;
}
__device__ __forceinline__ void tf_split(float v, uint32_t& hi, uint32_t& lo) {
    hi = f2tf(v);
    float r = v - __uint_as_float(hi);
    lo = f2tf(r);
}
__device__ __forceinline__ void mma8(float* c, const uint32_t* a, const uint32_t* b) {
    asm volatile(
        "mma.sync.aligned.m16n8k8.row.col.f32.tf32.tf32.f32 "
        "{%0,%1,%2,%3}, {%4,%5,%6,%7}, {%8,%9}, {%0,%1,%2,%3};"
        : "+f"(c[0]), "+f"(c[1]), "+f"(c[2]), "+f"(c[3])
        : "r"(a[0]), "r"(a[1]), "r"(a[2]), "r"(a[3]), "r"(b[0]), "r"(b[1]));
}

// ---------------------------------------------------------------------------
// Tensor-core GEMM (3xTF32, ~fp32 accuracy). 128x128 tile, BK=16, 256 thr.
// 8 warps in 4(m) x 2(n); each warp 32x64 via m16n8k8 tiles (2 x 8).
// EPI: 0 = plain, 1 = gelu(tanh), 2 = +bias1+bias2+resid, 3 = += C
// ---------------------------------------------------------------------------
template<int EPI>
__global__ __launch_bounds__(256) void tgemm_kernel(
    const float* __restrict__ A, const float* __restrict__ Bm,
    float* __restrict__ C,
    const float* __restrict__ bias1, const float* __restrict__ bias2,
    const float* __restrict__ resid,
    int M, int N, int K)
{
    // stride 136: 136 mod 32 = 8 -> fragment LDS conflict-free
    __shared__ float As[2][16][136];   // [k][m]
    __shared__ float Bs[2][16][136];   // [k][n]

    int tid  = threadIdx.x;
    int bm = blockIdx.y, bn = blockIdx.x;
    int warp = tid >> 5, lane = tid & 31;
    int wm = (warp & 3) * 32;          // warp row base in tile
    int wn = (warp >> 2) * 64;         // warp col base in tile
    int g  = lane >> 2, tg = lane & 3;

    // A load mapping: thread covers (row am, k-chunks ak & ak+8) as float4
    int am = tid & 127;
    int ak = (tid >> 7) * 4;           // 0 or 4
    // B load mapping: thread covers (k rows bk & bk+8, 4 cols) as float4
    int bk  = tid >> 5;                // 0..7
    int bn4 = (tid & 31) * 4;

    const float* Ap = A  + (size_t)(bm * 128 + am) * K + ak;
    const float* Bp = Bm + (size_t)bk * N + bn * 128 + bn4;

    float acc[2][8][4];
    #pragma unroll
    for (int i = 0; i < 2; i++)
        #pragma unroll
        for (int j = 0; j < 8; j++)
            #pragma unroll
            for (int r = 0; r < 4; r++) acc[i][j][r] = 0.0f;

    // prologue: stage 0
    {
        float4 a0 = *(const float4*)(Ap);
        float4 a1 = *(const float4*)(Ap + 8);
        float4 b0 = *(const float4*)(Bp);
        float4 b1 = *(const float4*)(Bp + (size_t)8 * N);
        As[0][ak+0][am] = a0.x; As[0][ak+1][am] = a0.y;
        As[0][ak+2][am] = a0.z; As[0][ak+3][am] = a0.w;
        As[0][ak+8][am] = a1.x; As[0][ak+9][am] = a1.y;
        As[0][ak+10][am] = a1.z; As[0][ak+11][am] = a1.w;
        *(float4*)&Bs[0][bk][bn4]     = b0;
        *(float4*)&Bs[0][bk + 8][bn4] = b1;
    }
    __syncthreads();

    int s = 0;
    for (int k0 = 0; k0 < K; k0 += 16) {
        float4 pa0, pa1, pb0, pb1;
        bool pre = (k0 + 16) < K;
        if (pre) {
            const float* Ap2 = Ap + k0 + 16;
            const float* Bp2 = Bp + (size_t)(k0 + 16) * N;
            pa0 = *(const float4*)(Ap2);
            pa1 = *(const float4*)(Ap2 + 8);
            pb0 = *(const float4*)(Bp2);
            pb1 = *(const float4*)(Bp2 + (size_t)8 * N);
        }

        #pragma unroll
        for (int ks = 0; ks < 2; ks++) {
            int kk = ks * 8;
            uint32_t ahi[2][4], alo[2][4];
            #pragma unroll
            for (int i = 0; i < 2; i++) {
                int m0 = wm + i * 16;
                tf_split(As[s][kk+tg  ][m0+g  ], ahi[i][0], alo[i][0]);
                tf_split(As[s][kk+tg  ][m0+g+8], ahi[i][1], alo[i][1]);
                tf_split(As[s][kk+tg+4][m0+g  ], ahi[i][2], alo[i][2]);
                tf_split(As[s][kk+tg+4][m0+g+8], ahi[i][3], alo[i][3]);
            }
            #pragma unroll
            for (int j = 0; j < 8; j++) {
                int n0 = wn + j * 8;
                uint32_t bhi[2], blo[2];
                tf_split(Bs[s][kk+tg  ][n0+g], bhi[0], blo[0]);
                tf_split(Bs[s][kk+tg+4][n0+g], bhi[1], blo[1]);
                #pragma unroll
                for (int i = 0; i < 2; i++) {
                    mma8(acc[i][j], ahi[i], bhi);
                    mma8(acc[i][j], alo[i], bhi);
                    mma8(acc[i][j], ahi[i], blo);
                }
            }
        }

        if (pre) {
            int sn = s ^ 1;
            As[sn][ak+0][am] = pa0.x; As[sn][ak+1][am] = pa0.y;
            As[sn][ak+2][am] = pa0.z; As[sn][ak+3][am] = pa0.w;
            As[sn][ak+8][am] = pa1.x; As[sn][ak+9][am] = pa1.y;
            As[sn][ak+10][am] = pa1.z; As[sn][ak+11][am] = pa1.w;
            *(float4*)&Bs[sn][bk][bn4]     = pb0;
            *(float4*)&Bs[sn][bk + 8][bn4] = pb1;
        }
        __syncthreads();
        s ^= 1;
    }

    // epilogue
    #pragma unroll
    for (int i = 0; i < 2; i++) {
        #pragma unroll
        for (int j = 0; j < 8; j++) {
            int row0 = bm * 128 + wm + i * 16 + g;
            int col  = bn * 128 + wn + j * 8 + tg * 2;
            #pragma unroll
            for (int rr = 0; rr < 2; rr++) {
                int row = row0 + rr * 8;
                size_t idx = (size_t)row * N + col;
                #pragma unroll
                for (int cc = 0; cc < 2; cc++) {
                    float val = acc[i][j][rr * 2 + cc];
                    if (EPI == 1) {
                        float t = 0.7978845608028654f *
                                  (val + 0.044715f * val * val * val);
                        val = 0.5f * val * (1.0f + tanhf(t));
                    } else if (EPI == 2) {
                        val += bias1[col + cc] + bias2[col + cc] + resid[idx + cc];
                    } else if (EPI == 3) {
                        val += C[idx + cc];
                    }
                    C[idx + cc] = val;
                }
            }
        }
    }
}

// ---------------------------------------------------------------------------
// Flash attention (fp32). Grid: (S/128, H, B). 128 threads, one query row per
// thread. K/V staged in SMEM in BK=32 tiles; all compute reads are broadcasts.
// ---------------------------------------------------------------------------
__global__ __launch_bounds__(128) void attn_kernel(
    const float* __restrict__ q, const float* __restrict__ k,
    const float* __restrict__ v, float* __restrict__ av)
{
    int h = blockIdx.y, b = blockIdx.z;
    int tid = threadIdx.x;
    int qi = blockIdx.x * 128 + tid;

    __shared__ float Ks[32][64];
    __shared__ float Vs[32][64];

    const float* qptr = q + ((size_t)(b * S_ + qi)) * D_ + h * HD_;
    float4 qr[16];
    #pragma unroll
    for (int i = 0; i < 16; i++) qr[i] = ((const float4*)qptr)[i];

    float4 acc[16];
    #pragma unroll
    for (int i = 0; i < 16; i++) acc[i] = make_float4(0.f, 0.f, 0.f, 0.f);

    float m = -1e30f, l = 0.0f;
    const float scale = 0.125f;  // 1/sqrt(64)

    int r = tid >> 2;
    int c = (tid & 3) * 16;

    for (int kt = 0; kt < S_; kt += 32) {
        __syncthreads();
        {
            const float* kp = k + ((size_t)(b * S_ + kt + r)) * D_ + h * HD_ + c;
            const float* vp = v + ((size_t)(b * S_ + kt + r)) * D_ + h * HD_ + c;
            #pragma unroll
            for (int i = 0; i < 4; i++) {
                *(float4*)&Ks[r][c + 4 * i] = ((const float4*)kp)[i];
                *(float4*)&Vs[r][c + 4 * i] = ((const float4*)vp)[i];
            }
        }
        __syncthreads();

        float s[32];
        float tmax = -1e30f;
        #pragma unroll
        for (int j = 0; j < 32; j++) {
            const float4* kr = (const float4*)Ks[j];
            float d0 = 0.f;
            #pragma unroll
            for (int i = 0; i < 16; i++) {
                float4 kk = kr[i];
                d0 = fmaf(qr[i].x, kk.x, d0);
                d0 = fmaf(qr[i].y, kk.y, d0);
                d0 = fmaf(qr[i].z, kk.z, d0);
                d0 = fmaf(qr[i].w, kk.w, d0);
            }
            s[j] = d0 * scale;
            tmax = fmaxf(tmax, s[j]);
        }

        float mnew = fmaxf(m, tmax);
        float corr = __expf(m - mnew);
        l *= corr;
        #pragma unroll
        for (int i = 0; i < 16; i++) {
            acc[i].x *= corr; acc[i].y *= corr;
            acc[i].z *= corr; acc[i].w *= corr;
        }
        m = mnew;

        #pragma unroll
        for (int j = 0; j < 32; j++) {
            float p = __expf(s[j] - m);
            l += p;
            const float4* vr = (const float4*)Vs[j];
            #pragma unroll
            for (int i = 0; i < 16; i++) {
                float4 vv = vr[i];
                acc[i].x = fmaf(p, vv.x, acc[i].x);
                acc[i].y = fmaf(p, vv.y, acc[i].y);
                acc[i].z = fmaf(p, vv.z, acc[i].z);
                acc[i].w = fmaf(p, vv.w, acc[i].w);
            }
        }
    }

    float invl = 1.0f / l;
    float* op = av + ((size_t)(b * S_ + qi)) * D_ + h * HD_;
    #pragma unroll
    for (int i = 0; i < 16; i++) {
        float4 o;
        o.x = acc[i].x * invl; o.y = acc[i].y * invl;
        o.z = acc[i].z * invl; o.w = acc[i].w * invl;
        ((float4*)op)[i] = o;
    }
}

// ---------------------------------------------------------------------------
// Launch
// ---------------------------------------------------------------------------
extern "C" void kernel_launch(void* const* d_in, const int* in_sizes, int n_in,
                              void* d_out, int out_size)
{
    const float* x          = (const float*)d_in[0];
    const float* pns        = (const float*)d_in[1];
    const float* w_mlp_in   = (const float*)d_in[2];
    const float* wq         = (const float*)d_in[3];
    const float* wk         = (const float*)d_in[4];
    const float* wv         = (const float*)d_in[5];
    const float* w_mlp_out  = (const float*)d_in[6];
    const float* b_mlp_out  = (const float*)d_in[7];
    const float* w_attn_out = (const float*)d_in[8];
    const float* b_attn_out = (const float*)d_in[9];
    float* out = (float*)d_out;

    float *xn, *hbuf, *q, *k, *v, *av;
    cudaGetSymbolAddress((void**)&xn,   g_xn);
    cudaGetSymbolAddress((void**)&hbuf, g_h);
    cudaGetSymbolAddress((void**)&q,    g_q);
    cudaGetSymbolAddress((void**)&k,    g_k);
    cudaGetSymbolAddress((void**)&v,    g_v);
    cudaGetSymbolAddress((void**)&av,   g_av);

    // 1. RMSNorm
    rmsnorm_kernel<<<MROWS, 256>>>(x, pns, xn);

    // 2. h = gelu(xn @ w_mlp_in)   [8192, 4096]
    dim3 g_mlp(MLP_ / 128, MROWS / 128);
    tgemm_kernel<1><<<g_mlp, 256>>>(xn, w_mlp_in, hbuf,
                                    nullptr, nullptr, nullptr,
                                    MROWS, MLP_, D_);

    // 3. q/k/v = xn @ w{q,k,v}    [8192, 1024] each
    dim3 g_d(D_ / 128, MROWS / 128);
    tgemm_kernel<0><<<g_d, 256>>>(xn, wq, q, nullptr, nullptr, nullptr,
                                  MROWS, D_, D_);
    tgemm_kernel<0><<<g_d, 256>>>(xn, wk, k, nullptr, nullptr, nullptr,
                                  MROWS, D_, D_);
    tgemm_kernel<0><<<g_d, 256>>>(xn, wv, v, nullptr, nullptr, nullptr,
                                  MROWS, D_, D_);

    // 4. attention -> av  [8192, 1024] (cols = h*64+hd)
    dim3 g_attn(S_ / 128, H_, B_);
    attn_kernel<<<g_attn, 128>>>(q, k, v, av);

    // 5. out = residual + h @ w_mlp_out + b_mlp_out + b_attn_out
    tgemm_kernel<2><<<g_d, 256>>>(hbuf, w_mlp_out, out,
                                  b_mlp_out, b_attn_out, x,
                                  MROWS, D_, MLP_);

    // 6. out += av @ w_attn_out
    tgemm_kernel<3><<<g_d, 256>>>(av, w_attn_out, out,
                                  nullptr, nullptr, nullptr,
                                  MROWS, D_, D_);
}